// round 11
// baseline (speedup 1.0000x reference)
#include <cuda_runtime.h>
#include <cstdint>
#include <cstddef>

// ---------------------------------------------------------------------------
// CrossAttentionDecoder: B=1024 (8*128), n_tok=16, num_latents=128, d=512,
// heads=8, dh=64.  Mask: batch b attends only to latents j <= (b % 128).
//
// Head-pair-split fully-fused formulation.  One CTA per (b, head-pair):
//   q_hp = x[b] @ Wq[:,hp]^T        (16x128, in-kernel)
//   qk   = q_h @ Wk_h               (per head, rank-64 absorption)
//   S    = qk @ l[b]^T,  P = softmax(S/8) masked
//   pl   = P @ l[b],  ov = pl @ Wv_h^T
//   out[b] += ov @ Wo[:, hp-slice]^T   (partial k=128, atomicAdd; bias via init)
// 256 threads, 66 KB smem, __launch_bounds__(256,3) -> 3 CTAs/SM target.
// ---------------------------------------------------------------------------

#define DIMK 512

__device__ float g_Wqf[64 * 64 * 32 * 2];
__device__ float g_Wvf[64 * 64 * 32 * 2];
__device__ float g_Wof[64 * 64 * 32 * 2];
__device__ float g_Wkf[8 * 64 * 8 * 32 * 2];        // transposed pack for qk

// ---------------- helpers ---------------------------------------------------
__device__ __forceinline__ float to_tf32(float x) {
    uint32_t u; asm("cvt.rna.tf32.f32 %0, %1;" : "=r"(u) : "f"(x));
    return __uint_as_float(u);
}
__device__ __forceinline__ uint32_t f2u(float x) { return __float_as_uint(x); }

__device__ __forceinline__ void mma_tf32(float* d, const uint32_t* a, const uint32_t* b) {
    asm volatile(
        "mma.sync.aligned.m16n8k8.row.col.f32.tf32.tf32.f32 "
        "{%0,%1,%2,%3}, {%4,%5,%6,%7}, {%8,%9}, {%0,%1,%2,%3};\n"
        : "+f"(d[0]), "+f"(d[1]), "+f"(d[2]), "+f"(d[3])
        : "r"(a[0]), "r"(a[1]), "r"(a[2]), "r"(a[3]),
          "r"(b[0]), "r"(b[1]));
}

// ---------------------------------------------------------------------------
// prep_w: fragment-pack Wq, Wv, Wo (B[n][k] = W[n][k]) and Wk transposed.
// ---------------------------------------------------------------------------
__global__ __launch_bounds__(256)
void prep_w(const float* __restrict__ Wq, const float* __restrict__ Wk,
            const float* __restrict__ Wv, const float* __restrict__ Wo)
{
    int gid = blockIdx.x * 256 + threadIdx.x;        // 2048 blocks
    int lane = gid & 31, kk = (gid >> 5) & 63, nv = gid >> 11;   // nv 0..255
    int g = lane >> 2, tg = lane & 3;
    if (nv < 192) {
        const float* W; float* dst; int dn;
        if (nv < 64)       { W = Wq; dst = g_Wqf; dn = nv; }
        else if (nv < 128) { W = Wv; dst = g_Wvf; dn = nv - 64; }
        else               { W = Wo; dst = g_Wof; dn = nv - 128; }
        float v0 = to_tf32(W[(size_t)(dn * 8 + g) * DIMK + kk * 8 + tg]);
        float v1 = to_tf32(W[(size_t)(dn * 8 + g) * DIMK + kk * 8 + tg + 4]);
        *(float2*)(dst + ((size_t)(dn * 64 + kk) * 32 + lane) * 2) = make_float2(v0, v1);
    } else {
        int t = nv - 192;            // 0..63
        int h = t >> 3, ks = t & 7;
        int ntg = kk;
        float v0 = to_tf32(Wk[(size_t)(h * 64 + ks * 8 + tg) * DIMK + ntg * 8 + g]);
        float v1 = to_tf32(Wk[(size_t)(h * 64 + ks * 8 + tg + 4) * DIMK + ntg * 8 + g]);
        *(float2*)(g_Wkf + ((size_t)((h * 64 + ntg) * 8 + ks) * 32 + lane) * 2) =
            make_float2(v0, v1);
    }
}

// ---------------------------------------------------------------------------
// init_out: out[r][c] = bo[c]  (bias pre-init; head-pair CTAs atomicAdd partials)
// ---------------------------------------------------------------------------
__global__ __launch_bounds__(256)
void init_out(const float* __restrict__ bo, float* __restrict__ out)
{
    size_t gid = (size_t)blockIdx.x * 256 + threadIdx.x;   // 8192 blocks
    float4 bv = *(const float4*)(bo + ((gid * 4) & 511));
    *(float4*)(out + gid * 4) = bv;
}

// ---------------------------------------------------------------------------
// fattn5: one CTA per (b, head-pair).  256 threads = 8 warps.
// Smem (floats): qf 2048 | qkc 2048 | lc 8704 | Pf 4096 = 16896 (66 KB)
// ---------------------------------------------------------------------------
#define F5_QF  0
#define F5_QKC 2048
#define F5_LC  4096
#define F5_PF  12800
#define F5_TOT 16896

__global__ __launch_bounds__(256, 3)
void fattn5(const float* __restrict__ x, const float* __restrict__ l,
            float* __restrict__ out)
{
    extern __shared__ __align__(16) float sm[];
    float* qf  = sm + F5_QF;
    float* qkc = sm + F5_QKC;
    float* lc  = sm + F5_LC;
    float* Pf  = sm + F5_PF;

    const int bid = blockIdx.x;
    const int hp = bid & 3;
    const int ib = bid >> 2;
    const int b = (ib & 7) * 128 + (127 - (ib >> 3));   // heavy-first
    const int nj = (b & 127) + 1;
    const int T = (nj + 7) >> 3;
    const int njc8 = T << 3;

    const int tid = threadIdx.x, w = tid >> 5, lane = tid & 31;
    const int g = lane >> 2, tg = lane & 3;
    const int amt = w >> 2, anc = w & 3;    // m-tile (head) / col-group; also wm/wn

    // conflict-free lc tile read offsets (R8-verified)
    const int p1o0 = g * 4 + tg;
    const int p1o1 = ((g ^ 4) + 8) * 4 + tg;
    const int h2 = g >> 2, gl = g & 3;
    const int p2o0 = ((tg ^ (h2 << 2)) + (h2 << 3)) * 4 + gl;
    const int p2o1 = (((tg + 4) ^ (h2 << 2)) + (h2 << 3)) * 4 + gl;

    // ---- stage x a-frags into lc region [kk 64][128] ----
    #pragma unroll
    for (int it = 0; it < 8; it++) {
        int i4 = tid + it * 256;             // 0..2047 float4s
        int i = i4 >> 7, c4 = (i4 & 127) * 4;
        float4 v = *(const float4*)(x + ((size_t)(b * 16 + i)) * 512 + c4);
        float vv[4] = {v.x, v.y, v.z, v.w};
        #pragma unroll
        for (int e = 0; e < 4; e++) {
            int c = c4 + e;
            lc[(c >> 3) * 128 + ((i & 7) * 4 + (c & 3)) * 4 +
               ((i >> 3) + 2 * ((c >> 2) & 1))] = to_tf32(vv[e]);
        }
    }
    __syncthreads();

    // ---- Q-proj: q cols [hp*128,+128); warp w -> 16 cols (nt=2) ----
    {
        float acc[2][4];
        #pragma unroll
        for (int nt = 0; nt < 2; nt++)
            #pragma unroll
            for (int c = 0; c < 4; c++) acc[nt][c] = 0.f;
        const float* wq0 = g_Wqf + ((size_t)(hp * 16 + w * 2) * 64) * 64 + lane * 2;
        uint2 bp0 = *(const uint2*)(wq0), bp1 = *(const uint2*)(wq0 + 4096);
        for (int kk = 0; kk < 64; kk++) {
            float4 af = *(const float4*)(lc + kk * 128 + lane * 4);
            uint32_t a[4] = {f2u(af.x), f2u(af.y), f2u(af.z), f2u(af.w)};
            uint2 bc0 = bp0, bc1 = bp1;
            if (kk < 63) {
                bp0 = *(const uint2*)(wq0 + (kk + 1) * 64);
                bp1 = *(const uint2*)(wq0 + 4096 + (kk + 1) * 64);
            }
            mma_tf32(acc[0], a, (const uint32_t*)&bc0);
            mma_tf32(acc[1], a, (const uint32_t*)&bc1);
        }
        __syncthreads();   // lc (x frags) dead
        #pragma unroll
        for (int nt = 0; nt < 2; nt++) {
            #pragma unroll
            for (int e = 0; e < 4; e++) {
                int cq = w * 16 + nt * 8 + 2 * tg + (e & 1);   // 0..127 local
                int lh = cq >> 6, ee = cq & 63;
                int ks = ee >> 3, kb = ee & 7;
                int i = g + 8 * (e >> 1);
                qf[(lh * 8 + ks) * 128 + ((i & 7) * 4 + (kb & 3)) * 4 +
                   ((i >> 3) + 2 * ((kb >> 2) & 1))] = to_tf32(acc[nt][e]);
            }
        }
    }
    __syncthreads();

    float sacc[4][4];
    #pragma unroll
    for (int j = 0; j < 4; j++)
        #pragma unroll
        for (int c = 0; c < 4; c++) sacc[j][c] = 0.f;

    // ================= pass 1: scores =================
    for (int ch = 0; ch < 8; ch++) {
        // l loads (j 0..63) first; phase A overlaps the latency
        float4 sv[4];
        #pragma unroll
        for (int it = 0; it < 4; it++) {
            int i4 = tid + it * 256;
            int j = i4 >> 4, dq = i4 & 15;
            sv[it] = make_float4(0.f, 0.f, 0.f, 0.f);
            if (j < nj)
                sv[it] = *(const float4*)(l + ((size_t)(b * 128 + j)) * 512 + ch * 64 + dq * 4);
        }
        // phase A: qk-chunk for head (hp*2+amt), 16 cols (nt=2)
        float aacc[2][4];
        #pragma unroll
        for (int nt = 0; nt < 2; nt++)
            #pragma unroll
            for (int c = 0; c < 4; c++) aacc[nt][c] = 0.f;
        {
            const float* wk0 = g_Wkf +
                ((size_t)(((hp * 2 + amt) * 64 + ch * 8 + anc * 2) * 8)) * 64 + lane * 2;
            uint2 bp0 = *(const uint2*)(wk0), bp1 = *(const uint2*)(wk0 + 512);
            #pragma unroll
            for (int ks = 0; ks < 8; ks++) {
                float4 af = *(const float4*)(qf + (amt * 8 + ks) * 128 + lane * 4);
                uint2 bc0 = bp0, bc1 = bp1;
                if (ks < 7) {
                    bp0 = *(const uint2*)(wk0 + (ks + 1) * 64);
                    bp1 = *(const uint2*)(wk0 + 512 + (ks + 1) * 64);
                }
                uint32_t a[4] = {f2u(af.x), f2u(af.y), f2u(af.z), f2u(af.w)};
                mma_tf32(aacc[0], a, (const uint32_t*)&bc0);
                mma_tf32(aacc[1], a, (const uint32_t*)&bc1);
            }
        }
        // STS batch1
        #pragma unroll
        for (int it = 0; it < 4; it++) {
            int i4 = tid + it * 256;
            int j = i4 >> 4, dq = i4 & 15;
            if (j < njc8) {
                int hh = dq & 1;
                int X = ((j & 7) ^ (hh << 2)) + (hh << 3);
                float4 o;
                o.x = to_tf32(sv[it].x); o.y = to_tf32(sv[it].y);
                o.z = to_tf32(sv[it].z); o.w = to_tf32(sv[it].w);
                *(float4*)(lc + ((j >> 3) * 8 + (dq >> 1)) * 68 + X * 4) = o;
            }
        }
        // batch2 (j 64..127) if needed
        if (njc8 > 64) {
            #pragma unroll
            for (int it = 4; it < 8; it++) {
                int i4 = tid + it * 256;
                int j = i4 >> 4, dq = i4 & 15;
                float4 v = make_float4(0.f, 0.f, 0.f, 0.f);
                if (j < nj)
                    v = *(const float4*)(l + ((size_t)(b * 128 + j)) * 512 + ch * 64 + dq * 4);
                if (j < njc8) {
                    int hh = dq & 1;
                    int X = ((j & 7) ^ (hh << 2)) + (hh << 3);
                    float4 o;
                    o.x = to_tf32(v.x); o.y = to_tf32(v.y);
                    o.z = to_tf32(v.z); o.w = to_tf32(v.w);
                    *(float4*)(lc + ((j >> 3) * 8 + (dq >> 1)) * 68 + X * 4) = o;
                }
            }
        }
        // scatter qk-chunk -> qkc a-frags
        #pragma unroll
        for (int nt = 0; nt < 2; nt++) {
            #pragma unroll
            for (int e = 0; e < 4; e++) {
                int d = anc * 16 + nt * 8 + 2 * tg + (e & 1);   // 0..63
                int ksd = d >> 3, kb = d & 7;
                qkc[((amt * 8 + ksd) * 32 + g * 4 + (kb & 3)) * 4 +
                    ((e >> 1) + 2 * ((kb >> 2) & 1))] = to_tf32(aacc[nt][e]);
            }
        }
        __syncthreads();

        // scores mma: warp (amt=wm, anc=wn), jt = anc + 4*jt4
        #pragma unroll
        for (int ksd = 0; ksd < 8; ksd++) {
            float4 af = *(const float4*)(qkc + ((amt * 8 + ksd) * 32 + lane) * 4);
            uint32_t a[4] = {f2u(af.x), f2u(af.y), f2u(af.z), f2u(af.w)};
            #pragma unroll
            for (int jt4 = 0; jt4 < 4; jt4++) {
                int jt = anc + jt4 * 4;
                if (jt < T) {
                    int tb = (jt * 8 + ksd) * 68;
                    uint32_t bu[2] = { f2u(lc[tb + p1o0]), f2u(lc[tb + p1o1]) };
                    mma_tf32(sacc[jt4], a, bu);
                }
            }
        }
        __syncthreads();
    }

    // ---- scatter scores -> Pf (a-frag layout, scaled) ----
    #pragma unroll
    for (int jt4 = 0; jt4 < 4; jt4++) {
        int jt = anc + jt4 * 4;
        if (jt < T) {
            #pragma unroll
            for (int e = 0; e < 4; e++) {
                int j = jt * 8 + 2 * tg + (e & 1);
                int rl = g + 8 * (e >> 1);
                Pf[(amt * 16 + jt) * 128 + ((rl & 7) * 4 + (j & 3)) * 4 +
                   ((rl >> 3) + 2 * ((j >> 2) & 1))] = sacc[jt4][e] * 0.125f;
            }
        }
    }
    __syncthreads();

    // ---- softmax: warp w owns rows w*4 .. w*4+3 (32 rows total) ----
    #pragma unroll
    for (int rr2 = 0; rr2 < 4; rr2++) {
        int row = w * 4 + rr2;
        int mt = row >> 4, rl = row & 15;
        int base = mt * 16 * 128 + ((rl & 7) * 4) * 4 + (rl >> 3);
        float mx = -1e30f;
        for (int j = lane; j < nj; j += 32)
            mx = fmaxf(mx, Pf[base + (j >> 3) * 128 + (j & 3) * 4 + 2 * ((j >> 2) & 1)]);
        #pragma unroll
        for (int o = 16; o; o >>= 1) mx = fmaxf(mx, __shfl_xor_sync(0xffffffffu, mx, o));
        float e4[4]; int cnt = 0; float s = 0.f;
        for (int j = lane; j < nj; j += 32) {
            float ev = __expf(Pf[base + (j >> 3) * 128 + (j & 3) * 4 + 2 * ((j >> 2) & 1)] - mx);
            e4[cnt++] = ev; s += ev;
        }
        #pragma unroll
        for (int o = 16; o; o >>= 1) s += __shfl_xor_sync(0xffffffffu, s, o);
        float inv = 1.f / s;
        cnt = 0;
        for (int j = lane; j < njc8; j += 32) {
            float val = (j < nj) ? e4[cnt++] * inv : 0.f;
            Pf[base + (j >> 3) * 128 + (j & 3) * 4 + 2 * ((j >> 2) & 1)] = to_tf32(val);
        }
    }

    // ================= pass 2: pl + ov =================
    float ovacc[2][4];
    #pragma unroll
    for (int nt = 0; nt < 2; nt++)
        #pragma unroll
        for (int c = 0; c < 4; c++) ovacc[nt][c] = 0.f;

    for (int ch = 0; ch < 8; ch++) {
        float4 sv[4];
        #pragma unroll
        for (int it = 0; it < 4; it++) {
            int i4 = tid + it * 256;
            int j = i4 >> 4, dq = i4 & 15;
            sv[it] = make_float4(0.f, 0.f, 0.f, 0.f);
            if (j < nj)
                sv[it] = *(const float4*)(l + ((size_t)(b * 128 + j)) * 512 + ch * 64 + dq * 4);
        }
        // ov(ch-1) overlaps loads
        if (ch > 0) {
            const float* wv0 = g_Wvf +
                ((size_t)(((hp * 2 + amt) * 8 + anc * 2) * 64 + (ch - 1) * 8)) * 64 + lane * 2;
            uint2 bp0 = *(const uint2*)(wv0), bp1 = *(const uint2*)(wv0 + 4096);
            #pragma unroll
            for (int ksd = 0; ksd < 8; ksd++) {
                float4 af = *(const float4*)(qkc + ((amt * 8 + ksd) * 32 + lane) * 4);
                uint2 bc0 = bp0, bc1 = bp1;
                if (ksd < 7) {
                    bp0 = *(const uint2*)(wv0 + (ksd + 1) * 64);
                    bp1 = *(const uint2*)(wv0 + 4096 + (ksd + 1) * 64);
                }
                uint32_t a[4] = {f2u(af.x), f2u(af.y), f2u(af.z), f2u(af.w)};
                mma_tf32(ovacc[0], a, (const uint32_t*)&bc0);
                mma_tf32(ovacc[1], a, (const uint32_t*)&bc1);
            }
        }
        // STS batch1
        #pragma unroll
        for (int it = 0; it < 4; it++) {
            int i4 = tid + it * 256;
            int j = i4 >> 4, dq = i4 & 15;
            if (j < njc8) {
                int hh = dq & 1;
                int X = ((j & 7) ^ (hh << 2)) + (hh << 3);
                float4 o;
                o.x = to_tf32(sv[it].x); o.y = to_tf32(sv[it].y);
                o.z = to_tf32(sv[it].z); o.w = to_tf32(sv[it].w);
                *(float4*)(lc + ((j >> 3) * 8 + (dq >> 1)) * 68 + X * 4) = o;
            }
        }
        if (njc8 > 64) {
            #pragma unroll
            for (int it = 4; it < 8; it++) {
                int i4 = tid + it * 256;
                int j = i4 >> 4, dq = i4 & 15;
                float4 v = make_float4(0.f, 0.f, 0.f, 0.f);
                if (j < nj)
                    v = *(const float4*)(l + ((size_t)(b * 128 + j)) * 512 + ch * 64 + dq * 4);
                if (j < njc8) {
                    int hh = dq & 1;
                    int X = ((j & 7) ^ (hh << 2)) + (hh << 3);
                    float4 o;
                    o.x = to_tf32(v.x); o.y = to_tf32(v.y);
                    o.z = to_tf32(v.z); o.w = to_tf32(v.w);
                    *(float4*)(lc + ((j >> 3) * 8 + (dq >> 1)) * 68 + X * 4) = o;
                }
            }
        }
        __syncthreads();

        // pl-chunk = P @ lc ; warp (amt rows-16, anc cols-16, nt=2)
        float placc[2][4];
        #pragma unroll
        for (int nt = 0; nt < 2; nt++)
            #pragma unroll
            for (int c = 0; c < 4; c++) placc[nt][c] = 0.f;
        for (int ksj = 0; ksj < T; ksj++) {
            float4 af = *(const float4*)(Pf + (amt * 16 + ksj) * 128 + lane * 4);
            uint32_t a[4] = {f2u(af.x), f2u(af.y), f2u(af.z), f2u(af.w)};
            #pragma unroll
            for (int nt = 0; nt < 2; nt++) {
                int tb = (ksj * 8 + anc * 2 + nt) * 68;
                uint32_t bu[2] = { f2u(lc[tb + p2o0]), f2u(lc[tb + p2o1]) };
                mma_tf32(placc[nt], a, bu);
            }
        }
        // scatter pl-chunk -> qkc a-frags
        #pragma unroll
        for (int nt = 0; nt < 2; nt++) {
            #pragma unroll
            for (int e = 0; e < 4; e++) {
                int d = anc * 16 + nt * 8 + 2 * tg + (e & 1);
                int ksd = d >> 3, kb = d & 7;
                qkc[((amt * 8 + ksd) * 32 + g * 4 + (kb & 3)) * 4 +
                    ((e >> 1) + 2 * ((kb >> 2) & 1))] = to_tf32(placc[nt][e]);
            }
        }
        __syncthreads();
    }

    // ---- final ov(7) ----
    {
        const float* wv0 = g_Wvf +
            ((size_t)(((hp * 2 + amt) * 8 + anc * 2) * 64 + 7 * 8)) * 64 + lane * 2;
        uint2 bp0 = *(const uint2*)(wv0), bp1 = *(const uint2*)(wv0 + 4096);
        #pragma unroll
        for (int ksd = 0; ksd < 8; ksd++) {
            float4 af = *(const float4*)(qkc + ((amt * 8 + ksd) * 32 + lane) * 4);
            uint2 bc0 = bp0, bc1 = bp1;
            if (ksd < 7) {
                bp0 = *(const uint2*)(wv0 + (ksd + 1) * 64);
                bp1 = *(const uint2*)(wv0 + 4096 + (ksd + 1) * 64);
            }
            uint32_t a[4] = {f2u(af.x), f2u(af.y), f2u(af.z), f2u(af.w)};
            mma_tf32(ovacc[0], a, (const uint32_t*)&bc0);
            mma_tf32(ovacc[1], a, (const uint32_t*)&bc1);
        }
    }
    __syncthreads();   // all ov reads of qkc complete

    // ---- scatter ov -> qkc as O-proj a-frags [kk 16][128] ----
    #pragma unroll
    for (int nt = 0; nt < 2; nt++) {
        #pragma unroll
        for (int e = 0; e < 4; e++) {
            int vc = amt * 64 + anc * 16 + nt * 8 + 2 * tg + (e & 1);   // 0..127
            int kk = vc >> 3, kb = vc & 7;
            int i = g + 8 * (e >> 1);
            qkc[kk * 128 + ((i & 7) * 4 + (kb & 3)) * 4 +
                ((i >> 3) + 2 * ((kb >> 2) & 1))] = to_tf32(ovacc[nt][e]);
        }
    }
    __syncthreads();

    // ---- partial O-proj: out[b] += ov @ Wo[:, hp*128:+128]^T ----
    {
        float acc[8][4];
        #pragma unroll
        for (int nt = 0; nt < 8; nt++)
            #pragma unroll
            for (int c = 0; c < 4; c++) acc[nt][c] = 0.f;
        const float* wo0 = g_Wof + ((size_t)(w * 8) * 64 + hp * 16) * 64 + lane * 2;
        uint2 bp[8];
        #pragma unroll
        for (int nt = 0; nt < 8; nt++) bp[nt] = *(const uint2*)(wo0 + nt * 4096);
        for (int kk = 0; kk < 16; kk++) {
            float4 af = *(const float4*)(qkc + kk * 128 + lane * 4);
            uint32_t a[4] = {f2u(af.x), f2u(af.y), f2u(af.z), f2u(af.w)};
            uint2 bc[8];
            #pragma unroll
            for (int nt = 0; nt < 8; nt++) bc[nt] = bp[nt];
            if (kk < 15) {
                #pragma unroll
                for (int nt = 0; nt < 8; nt++)
                    bp[nt] = *(const uint2*)(wo0 + nt * 4096 + (kk + 1) * 64);
            }
            #pragma unroll
            for (int nt = 0; nt < 8; nt++)
                mma_tf32(acc[nt], a, (const uint32_t*)&bc[nt]);
        }
        #pragma unroll
        for (int nt = 0; nt < 8; nt++) {
            int c = w * 64 + nt * 8 + 2 * tg;
            float* o0 = out + ((size_t)(b * 16 + g)) * 512 + c;
            float* o1 = out + ((size_t)(b * 16 + g + 8)) * 512 + c;
            atomicAdd(o0,     acc[nt][0]);
            atomicAdd(o0 + 1, acc[nt][1]);
            atomicAdd(o1,     acc[nt][2]);
            atomicAdd(o1 + 1, acc[nt][3]);
        }
    }
}

// ---------------------------------------------------------------------------
extern "C" void kernel_launch(void* const* d_in, const int* in_sizes, int n_in,
                              void* d_out, int out_size)
{
    const float* x  = (const float*)d_in[0];
    const float* l  = (const float*)d_in[1];
    const float* Wq = (const float*)d_in[2];
    const float* Wk = (const float*)d_in[3];
    const float* Wv = (const float*)d_in[4];
    const float* Wo = (const float*)d_in[5];
    const float* bo = (const float*)d_in[6];
    float* out = (float*)d_out;

    const int smem_f = F5_TOT * 4;           // 67584
    cudaFuncSetAttribute(fattn5, cudaFuncAttributeMaxDynamicSharedMemorySize, smem_f);

    prep_w<<<2048, 256>>>(Wq, Wk, Wv, Wo);
    init_out<<<8192, 256>>>(bo, out);        // launch-order guarantees init < adds
    fattn5<<<4096, 256, smem_f>>>(x, l, out);
}

// round 12
// speedup vs baseline: 1.3150x; 1.3150x over previous
#include <cuda_runtime.h>
#include <cstdint>
#include <cstddef>

// ---------------------------------------------------------------------------
// CrossAttentionDecoder: B=1024 (8*128), n_tok=16, num_latents=128, d=512,
// heads=8, dh=64.  Mask: batch b attends only to latents j <= (b % 128).
//
// Fully-fused, one CTA per batch b (512 threads), superchunked d-loop:
//   q  = x[b] @ Wq^T                  (in-kernel)
//   qk = q_h @ Wk_h  (rank-64 absorption), S = qk @ l^T, P = softmax(S/8)
//   pl = P @ l,  ov = pl @ Wv_h^T,  out[b] = ov @ Wo^T + bo
// d processed in 4 superchunks of 128 (two 64-halves per sync block):
// half the barriers of the R9 kernel.  P stored a-frag packed (Pf), unioned
// with the q-fragment buffer (q dead after last phase A).
// ---------------------------------------------------------------------------

#define DIMK 512

__device__ float g_Wqf[64 * 64 * 32 * 2];
__device__ float g_Wvf[64 * 64 * 32 * 2];
__device__ float g_Wof[64 * 64 * 32 * 2];
__device__ float g_Wkf[8 * 64 * 8 * 32 * 2];        // transposed pack for qk

// ---------------- helpers ---------------------------------------------------
__device__ __forceinline__ float to_tf32(float x) {
    uint32_t u; asm("cvt.rna.tf32.f32 %0, %1;" : "=r"(u) : "f"(x));
    return __uint_as_float(u);
}
__device__ __forceinline__ uint32_t f2u(float x) { return __float_as_uint(x); }

__device__ __forceinline__ void mma_tf32(float* d, const uint32_t* a, const uint32_t* b) {
    asm volatile(
        "mma.sync.aligned.m16n8k8.row.col.f32.tf32.tf32.f32 "
        "{%0,%1,%2,%3}, {%4,%5,%6,%7}, {%8,%9}, {%0,%1,%2,%3};\n"
        : "+f"(d[0]), "+f"(d[1]), "+f"(d[2]), "+f"(d[3])
        : "r"(a[0]), "r"(a[1]), "r"(a[2]), "r"(a[3]),
          "r"(b[0]), "r"(b[1]));
}

// ---------------------------------------------------------------------------
// prep_w: fragment-pack Wq, Wv, Wo (B[n][k] = W[n][k]) and Wk transposed.
// ---------------------------------------------------------------------------
__global__ __launch_bounds__(256)
void prep_w(const float* __restrict__ Wq, const float* __restrict__ Wk,
            const float* __restrict__ Wv, const float* __restrict__ Wo)
{
    int gid = blockIdx.x * 256 + threadIdx.x;        // 2048 blocks
    int lane = gid & 31, kk = (gid >> 5) & 63, nv = gid >> 11;   // nv 0..255
    int g = lane >> 2, tg = lane & 3;
    if (nv < 192) {
        const float* W; float* dst; int dn;
        if (nv < 64)       { W = Wq; dst = g_Wqf; dn = nv; }
        else if (nv < 128) { W = Wv; dst = g_Wvf; dn = nv - 64; }
        else               { W = Wo; dst = g_Wof; dn = nv - 128; }
        float v0 = to_tf32(W[(size_t)(dn * 8 + g) * DIMK + kk * 8 + tg]);
        float v1 = to_tf32(W[(size_t)(dn * 8 + g) * DIMK + kk * 8 + tg + 4]);
        *(float2*)(dst + ((size_t)(dn * 64 + kk) * 32 + lane) * 2) = make_float2(v0, v1);
    } else {
        int t = nv - 192;            // 0..63
        int h = t >> 3, ks = t & 7;
        int ntg = kk;
        float v0 = to_tf32(Wk[(size_t)(h * 64 + ks * 8 + tg) * DIMK + ntg * 8 + g]);
        float v1 = to_tf32(Wk[(size_t)(h * 64 + ks * 8 + tg + 4) * DIMK + ntg * 8 + g]);
        *(float2*)(g_Wkf + ((size_t)((h * 64 + ntg) * 8 + ks) * 32 + lane) * 2) =
            make_float2(v0, v1);
    }
}

// ---------------------------------------------------------------------------
// fattn6: one CTA per batch b (heavy-first order), 512 threads (16 warps).
// Smem (floats): R 16384 (qf pass1 / Pf after) | qkc 16384 | lc 17408
//   = 50176 floats = 196 KB
// ---------------------------------------------------------------------------
#define F6_R   0
#define F6_QKC 16384
#define F6_LC  32768
#define F6_TOT 50176

__global__ __launch_bounds__(512, 1)
void fattn6(const float* __restrict__ x, const float* __restrict__ l,
            const float* __restrict__ bo, float* __restrict__ out)
{
    extern __shared__ __align__(16) float sm[];
    float* qf  = sm + F6_R;      // pass1: q a-frags [8h][8ks][128]
    float* Pf  = sm + F6_R;      // post-pass1: P a-frags [8mt][16ksj][128]
    float* qkc = sm + F6_QKC;    // qk/pl a-frags [8mt][16ksd][128]; also x/ov frags
    float* lc  = sm + F6_LC;     // l tiles [jt16][dtile16] x 68

    const int bid = blockIdx.x;
    const int b = (bid & 7) * 128 + (127 - (bid >> 3));   // heavy-first
    const int nj = (b & 127) + 1;
    const int T = (nj + 7) >> 3;
    const int njc8 = T << 3;

    const int tid = threadIdx.x, w = tid >> 5, lane = tid & 31;
    const int g = lane >> 2, tg = lane & 3;
    const int wm = w >> 2, wn = w & 3;        // scores mapping
    const int amt = w >> 1, anh = w & 1;      // phase A / pass2 / ov mapping

    // conflict-free lc tile read offsets (R8-verified)
    const int p1o0 = g * 4 + tg;
    const int p1o1 = ((g ^ 4) + 8) * 4 + tg;
    const int h2 = g >> 2, gl = g & 3;
    const int p2o0 = ((tg ^ (h2 << 2)) + (h2 << 3)) * 4 + gl;
    const int p2o1 = (((tg + 4) ^ (h2 << 2)) + (h2 << 3)) * 4 + gl;

    // ============ prologue: stage x a-frags into qkc ============
    #pragma unroll
    for (int it = 0; it < 4; it++) {
        int idx = tid + it * 512;           // 0..2047
        int i = idx >> 7, c4 = (idx & 127) * 4;
        float4 v = *(const float4*)(x + ((size_t)(b * 16 + i)) * 512 + c4);
        float vv[4] = {v.x, v.y, v.z, v.w};
        #pragma unroll
        for (int e = 0; e < 4; e++) {
            int c = c4 + e;
            qkc[(c >> 3) * 128 + ((i & 7) * 4 + (c & 3)) * 4 +
                ((i >> 3) + 2 * ((c >> 2) & 1))] = to_tf32(vv[e]);
        }
    }
    __syncthreads();

    // ============ Q-proj: q = x @ Wq^T -> qf (per-head a-frags) ============
    {
        float acc[4][4];
        #pragma unroll
        for (int nt = 0; nt < 4; nt++)
            #pragma unroll
            for (int c = 0; c < 4; c++) acc[nt][c] = 0.f;
        const float* wqb = g_Wqf + ((size_t)(w * 4) * 64) * 64 + lane * 2;
        uint2 bp[4];
        #pragma unroll
        for (int nt = 0; nt < 4; nt++) bp[nt] = *(const uint2*)(wqb + nt * 4096);
        for (int kk = 0; kk < 64; kk++) {
            float4 af = *(const float4*)(qkc + kk * 128 + lane * 4);
            uint32_t a[4] = {f2u(af.x), f2u(af.y), f2u(af.z), f2u(af.w)};
            uint2 bc[4];
            #pragma unroll
            for (int nt = 0; nt < 4; nt++) bc[nt] = bp[nt];
            if (kk < 63) {
                #pragma unroll
                for (int nt = 0; nt < 4; nt++)
                    bp[nt] = *(const uint2*)(wqb + nt * 4096 + (kk + 1) * 64);
            }
            #pragma unroll
            for (int nt = 0; nt < 4; nt++)
                mma_tf32(acc[nt], a, (const uint32_t*)&bc[nt]);
        }
        __syncthreads();   // qkc (x-frags) dead after all warps' reads
        #pragma unroll
        for (int nt = 0; nt < 4; nt++) {
            int c0 = w * 32 + nt * 8 + 2 * tg;
            #pragma unroll
            for (int e = 0; e < 4; e++) {
                int r = g + ((e >> 1) << 3);
                int c = c0 + (e & 1);
                int h = c >> 6, ks = (c & 63) >> 3;
                qf[(h * 8 + ks) * 128 + (g * 4 + (c & 3)) * 4 +
                   ((r >> 3) + 2 * ((c >> 2) & 1))] = to_tf32(acc[nt][e]);
            }
        }
    }
    __syncthreads();

    float sacc[2][4][4];
    #pragma unroll
    for (int i = 0; i < 2; i++)
        #pragma unroll
        for (int j = 0; j < 4; j++)
            #pragma unroll
            for (int c = 0; c < 4; c++) sacc[i][j][c] = 0.f;

    // ================= pass 1: scores, 4 superchunks of 128 d =================
    for (int ch2 = 0; ch2 < 4; ch2++) {
        #pragma unroll
        for (int sub = 0; sub < 2; sub++) {
            const int d0 = ch2 * 128 + sub * 64;
            // l loads first; phase A overlaps the latency
            float4 sv[4];
            #pragma unroll
            for (int it = 0; it < 4; it++) {
                int i4 = tid + it * 512;
                int j = i4 >> 4, dq = i4 & 15;
                sv[it] = make_float4(0.f, 0.f, 0.f, 0.f);
                if (j < nj)
                    sv[it] = *(const float4*)(l + ((size_t)(b * 128 + j)) * 512 + d0 + dq * 4);
            }
            // phase A: qk d-cols [d0, d0+64) for head amt
            float aacc[4][4];
            #pragma unroll
            for (int nt = 0; nt < 4; nt++)
                #pragma unroll
                for (int c = 0; c < 4; c++) aacc[nt][c] = 0.f;
            {
                const float* wkb = g_Wkf +
                    ((size_t)(amt * 64 + ch2 * 16 + sub * 8 + anh * 4)) * 512 + lane * 2;
                uint2 bp[4];
                #pragma unroll
                for (int nt = 0; nt < 4; nt++) bp[nt] = *(const uint2*)(wkb + nt * 512);
                #pragma unroll
                for (int ks = 0; ks < 8; ks++) {
                    float4 ac = *(const float4*)(qf + (amt * 8 + ks) * 128 + lane * 4);
                    uint2 bc[4];
                    #pragma unroll
                    for (int nt = 0; nt < 4; nt++) bc[nt] = bp[nt];
                    if (ks < 7) {
                        #pragma unroll
                        for (int nt = 0; nt < 4; nt++)
                            bp[nt] = *(const uint2*)(wkb + nt * 512 + (ks + 1) * 64);
                    }
                    uint32_t a[4] = {f2u(ac.x), f2u(ac.y), f2u(ac.z), f2u(ac.w)};
                    #pragma unroll
                    for (int nt = 0; nt < 4; nt++)
                        mma_tf32(aacc[nt], a, (const uint32_t*)&bc[nt]);
                }
            }
            // scatter qk-half into qkc a-frags (superchunk ksd = sub*8 + ..)
            #pragma unroll
            for (int nt = 0; nt < 4; nt++) {
                int c0 = anh * 32 + nt * 8 + 2 * tg;
                #pragma unroll
                for (int e = 0; e < 4; e++) {
                    int c = c0 + (e & 1);
                    qkc[((amt * 16 + sub * 8 + (c >> 3)) * 32 + g * 4 + (c & 3)) * 4 +
                        ((e >> 1) + 2 * ((c >> 2) & 1))] = to_tf32(aacc[nt][e]);
                }
            }
            // lc STS (tiles [jt][sub*8 + dtile])
            #pragma unroll
            for (int it = 0; it < 4; it++) {
                int i4 = tid + it * 512;
                int j = i4 >> 4, dq = i4 & 15;
                if (j < njc8) {
                    int hh = dq & 1;
                    int X = ((j & 7) ^ (hh << 2)) + (hh << 3);
                    float4 o;
                    o.x = to_tf32(sv[it].x); o.y = to_tf32(sv[it].y);
                    o.z = to_tf32(sv[it].z); o.w = to_tf32(sv[it].w);
                    *(float4*)(lc + ((j >> 3) * 16 + sub * 8 + (dq >> 1)) * 68 + X * 4) = o;
                }
            }
        }
        __syncthreads();

        // scores mma over 16 d-tiles
        #pragma unroll
        for (int ksd = 0; ksd < 16; ksd++) {
            float4 af0 = *(const float4*)(qkc + ((wm * 2 + 0) * 16 + ksd) * 128 + lane * 4);
            float4 af1 = *(const float4*)(qkc + ((wm * 2 + 1) * 16 + ksd) * 128 + lane * 4);
            uint32_t a0[4] = {f2u(af0.x), f2u(af0.y), f2u(af0.z), f2u(af0.w)};
            uint32_t a1[4] = {f2u(af1.x), f2u(af1.y), f2u(af1.z), f2u(af1.w)};
            #pragma unroll
            for (int jt4 = 0; jt4 < 4; jt4++) {
                int jt = wn + jt4 * 4;
                if (jt < T) {
                    int tb = (jt * 16 + ksd) * 68;
                    uint32_t bu[2] = { f2u(lc[tb + p1o0]), f2u(lc[tb + p1o1]) };
                    mma_tf32(sacc[0][jt4], a0, bu);
                    mma_tf32(sacc[1][jt4], a1, bu);
                }
            }
        }
        __syncthreads();
    }

    // ---- scatter scores -> Pf (a-frag layout, scaled); Pf overlays dead qf ----
    #pragma unroll
    for (int mt = 0; mt < 2; mt++) {
        #pragma unroll
        for (int jt4 = 0; jt4 < 4; jt4++) {
            int jt = wn + jt4 * 4;
            if (jt < T) {
                #pragma unroll
                for (int e = 0; e < 4; e++) {
                    int j = jt * 8 + 2 * tg + (e & 1);
                    Pf[((wm * 2 + mt) * 16 + jt) * 128 + (g * 4 + (j & 3)) * 4 +
                       ((e >> 1) + 2 * ((j >> 2) & 1))] = sacc[mt][jt4][e] * 0.125f;
                }
            }
        }
    }
    __syncthreads();

    // ---- softmax: warp w owns rows w*8 .. w*8+7 (packed-frag addressing) ----
    #pragma unroll
    for (int rr = 0; rr < 8; rr++) {
        int row = w * 8 + rr;
        int mt = row >> 4, rl = row & 15;
        int base = mt * 16 * 128 + ((rl & 7) * 4) * 4 + (rl >> 3);
        float mx = -1e30f;
        for (int j = lane; j < nj; j += 32)
            mx = fmaxf(mx, Pf[base + (j >> 3) * 128 + (j & 3) * 4 + 2 * ((j >> 2) & 1)]);
        #pragma unroll
        for (int o = 16; o; o >>= 1) mx = fmaxf(mx, __shfl_xor_sync(0xffffffffu, mx, o));
        float e4[4]; int cnt = 0; float s = 0.f;
        for (int j = lane; j < nj; j += 32) {
            float ev = __expf(Pf[base + (j >> 3) * 128 + (j & 3) * 4 + 2 * ((j >> 2) & 1)] - mx);
            e4[cnt++] = ev; s += ev;
        }
        #pragma unroll
        for (int o = 16; o; o >>= 1) s += __shfl_xor_sync(0xffffffffu, s, o);
        float inv = 1.f / s;
        cnt = 0;
        for (int j = lane; j < njc8; j += 32) {
            float val = (j < nj) ? e4[cnt++] * inv : 0.f;
            Pf[base + (j >> 3) * 128 + (j & 3) * 4 + 2 * ((j >> 2) & 1)] = to_tf32(val);
        }
    }

    // ================= pass 2: pl + ov, 4 superchunks =================
    float ovacc[4][4];
    #pragma unroll
    for (int nt = 0; nt < 4; nt++)
        #pragma unroll
        for (int c = 0; c < 4; c++) ovacc[nt][c] = 0.f;

    for (int ch2 = 0; ch2 < 4; ch2++) {
        #pragma unroll
        for (int sub = 0; sub < 2; sub++) {
            const int d0 = ch2 * 128 + sub * 64;
            float4 sv[4];
            #pragma unroll
            for (int it = 0; it < 4; it++) {
                int i4 = tid + it * 512;
                int j = i4 >> 4, dq = i4 & 15;
                sv[it] = make_float4(0.f, 0.f, 0.f, 0.f);
                if (j < nj)
                    sv[it] = *(const float4*)(l + ((size_t)(b * 128 + j)) * 512 + d0 + dq * 4);
            }
            // ov for previous superchunk, half 'sub' (overlaps loads)
            if (ch2 > 0) {
                const float* wvb = g_Wvf + (size_t)(amt * 8 + anh * 4) * 4096 +
                                   ((ch2 - 1) * 16 + sub * 8) * 64 + lane * 2;
                uint2 bp[4];
                #pragma unroll
                for (int nt = 0; nt < 4; nt++) bp[nt] = *(const uint2*)(wvb + nt * 4096);
                #pragma unroll
                for (int ksd = 0; ksd < 8; ksd++) {
                    float4 af = *(const float4*)(qkc +
                        ((amt * 16 + sub * 8 + ksd)) * 128 + lane * 4);
                    uint2 bc[4];
                    #pragma unroll
                    for (int nt = 0; nt < 4; nt++) bc[nt] = bp[nt];
                    if (ksd < 7) {
                        #pragma unroll
                        for (int nt = 0; nt < 4; nt++)
                            bp[nt] = *(const uint2*)(wvb + nt * 4096 + (ksd + 1) * 64);
                    }
                    uint32_t a[4] = {f2u(af.x), f2u(af.y), f2u(af.z), f2u(af.w)};
                    #pragma unroll
                    for (int nt = 0; nt < 4; nt++)
                        mma_tf32(ovacc[nt], a, (const uint32_t*)&bc[nt]);
                }
            }
            // lc STS
            #pragma unroll
            for (int it = 0; it < 4; it++) {
                int i4 = tid + it * 512;
                int j = i4 >> 4, dq = i4 & 15;
                if (j < njc8) {
                    int hh = dq & 1;
                    int X = ((j & 7) ^ (hh << 2)) + (hh << 3);
                    float4 o;
                    o.x = to_tf32(sv[it].x); o.y = to_tf32(sv[it].y);
                    o.z = to_tf32(sv[it].z); o.w = to_tf32(sv[it].w);
                    *(float4*)(lc + ((j >> 3) * 16 + sub * 8 + (dq >> 1)) * 68 + X * 4) = o;
                }
            }
        }
        __syncthreads();

        // pl over both halves -> qkc
        #pragma unroll
        for (int sub = 0; sub < 2; sub++) {
            float placc[4][4];
            #pragma unroll
            for (int nt = 0; nt < 4; nt++)
                #pragma unroll
                for (int c = 0; c < 4; c++) placc[nt][c] = 0.f;
            for (int ksj = 0; ksj < T; ksj++) {
                float4 af = *(const float4*)(Pf + (amt * 16 + ksj) * 128 + lane * 4);
                uint32_t a[4] = {f2u(af.x), f2u(af.y), f2u(af.z), f2u(af.w)};
                #pragma unroll
                for (int nt = 0; nt < 4; nt++) {
                    int tb = (ksj * 16 + sub * 8 + anh * 4 + nt) * 68;
                    uint32_t bu[2] = { f2u(lc[tb + p2o0]), f2u(lc[tb + p2o1]) };
                    mma_tf32(placc[nt], a, bu);
                }
            }
            #pragma unroll
            for (int nt = 0; nt < 4; nt++) {
                int c0 = anh * 32 + nt * 8 + 2 * tg;
                #pragma unroll
                for (int e = 0; e < 4; e++) {
                    int c = c0 + (e & 1);
                    qkc[((amt * 16 + sub * 8 + (c >> 3)) * 32 + g * 4 + (c & 3)) * 4 +
                        ((e >> 1) + 2 * ((c >> 2) & 1))] = to_tf32(placc[nt][e]);
                }
            }
        }
        __syncthreads();
    }

    // ---- final ov (superchunk 3, both halves) ----
    #pragma unroll
    for (int sub = 0; sub < 2; sub++) {
        const float* wvb = g_Wvf + (size_t)(amt * 8 + anh * 4) * 4096 +
                           (3 * 16 + sub * 8) * 64 + lane * 2;
        uint2 bp[4];
        #pragma unroll
        for (int nt = 0; nt < 4; nt++) bp[nt] = *(const uint2*)(wvb + nt * 4096);
        #pragma unroll
        for (int ksd = 0; ksd < 8; ksd++) {
            float4 af = *(const float4*)(qkc + ((amt * 16 + sub * 8 + ksd)) * 128 + lane * 4);
            uint2 bc[4];
            #pragma unroll
            for (int nt = 0; nt < 4; nt++) bc[nt] = bp[nt];
            if (ksd < 7) {
                #pragma unroll
                for (int nt = 0; nt < 4; nt++)
                    bp[nt] = *(const uint2*)(wvb + nt * 4096 + (ksd + 1) * 64);
            }
            uint32_t a[4] = {f2u(af.x), f2u(af.y), f2u(af.z), f2u(af.w)};
            #pragma unroll
            for (int nt = 0; nt < 4; nt++)
                mma_tf32(ovacc[nt], a, (const uint32_t*)&bc[nt]);
        }
    }
    __syncthreads();   // all ov reads of qkc complete

    // ============ epilogue: ov -> a-frags, out = ov @ Wo^T + bo ============
    #pragma unroll
    for (int nt = 0; nt < 4; nt++) {
        int c0 = amt * 64 + anh * 32 + nt * 8 + 2 * tg;
        #pragma unroll
        for (int e = 0; e < 4; e++) {
            int r = g + ((e >> 1) << 3);          // token i
            int c = c0 + (e & 1);
            qkc[(c >> 3) * 128 + (g * 4 + (c & 3)) * 4 +
                ((r >> 3) + 2 * ((c >> 2) & 1))] = to_tf32(ovacc[nt][e]);
        }
    }
    __syncthreads();

    {
        float acc[4][4];
        #pragma unroll
        for (int nt = 0; nt < 4; nt++)
            #pragma unroll
            for (int c = 0; c < 4; c++) acc[nt][c] = 0.f;
        const float* wob = g_Wof + ((size_t)(w * 4) * 64) * 64 + lane * 2;
        uint2 bp[4];
        #pragma unroll
        for (int nt = 0; nt < 4; nt++) bp[nt] = *(const uint2*)(wob + nt * 4096);
        for (int kk = 0; kk < 64; kk++) {
            float4 af = *(const float4*)(qkc + kk * 128 + lane * 4);
            uint32_t a[4] = {f2u(af.x), f2u(af.y), f2u(af.z), f2u(af.w)};
            uint2 bc[4];
            #pragma unroll
            for (int nt = 0; nt < 4; nt++) bc[nt] = bp[nt];
            if (kk < 63) {
                #pragma unroll
                for (int nt = 0; nt < 4; nt++)
                    bp[nt] = *(const uint2*)(wob + nt * 4096 + (kk + 1) * 64);
            }
            #pragma unroll
            for (int nt = 0; nt < 4; nt++)
                mma_tf32(acc[nt], a, (const uint32_t*)&bc[nt]);
        }
        #pragma unroll
        for (int nt = 0; nt < 4; nt++) {
            int c = w * 32 + nt * 8 + 2 * tg;
            float2 bb = *(const float2*)(bo + c);
            *(float2*)(out + ((size_t)(b * 16 + g)) * 512 + c) =
                make_float2(acc[nt][0] + bb.x, acc[nt][1] + bb.y);
            *(float2*)(out + ((size_t)(b * 16 + g + 8)) * 512 + c) =
                make_float2(acc[nt][2] + bb.x, acc[nt][3] + bb.y);
        }
    }
}

// ---------------------------------------------------------------------------
extern "C" void kernel_launch(void* const* d_in, const int* in_sizes, int n_in,
                              void* d_out, int out_size)
{
    const float* x  = (const float*)d_in[0];
    const float* l  = (const float*)d_in[1];
    const float* Wq = (const float*)d_in[2];
    const float* Wk = (const float*)d_in[3];
    const float* Wv = (const float*)d_in[4];
    const float* Wo = (const float*)d_in[5];
    const float* bo = (const float*)d_in[6];
    float* out = (float*)d_out;

    const int smem_f = F6_TOT * 4;           // 200704
    cudaFuncSetAttribute(fattn6, cudaFuncAttributeMaxDynamicSharedMemorySize, smem_f);

    prep_w<<<2048, 256>>>(Wq, Wk, Wv, Wo);
    fattn6<<<1024, 512, smem_f>>>(x, l, bo, out);
}